// round 5
// baseline (speedup 1.0000x reference)
#include <cuda_runtime.h>
#include <cuda_fp16.h>
#include <cstdint>

// Problem constants
constexpr int B  = 8;
constexpr int C  = 256;
constexpr int H  = 64;
constexpr int W  = 64;
constexpr int HW = H * W;          // 4096
constexpr int K2 = 9;
constexpr int DG = 4;
constexpr int CG = C / DG;         // 64
constexpr int CK = C * K2;         // 2304
constexpr int GN = 32;
constexpr int CPG = C / GN;        // 8

// Scratch (static device arrays)
__device__ __align__(16) __half g_A[(size_t)C * CK];            // fp16 weights [m][ck]
__device__ __align__(16) float2 g_off[(size_t)B * DG * K2 * HW];// offsets (dy,dx) 9.4 MB
__device__ float g_conv[(size_t)B * C * HW];                    // 33.5 MB conv output
__device__ float g_gsum[B * GN];
__device__ float g_gss[B * GN];

// ---------------------------------------------------------------------------
// PTX helpers (baseline PTX only — toolchain targets compute_103, no tcgen05)
// ---------------------------------------------------------------------------
__device__ __forceinline__ uint32_t smem_u32(const void* p) {
    uint32_t a;
    asm("{ .reg .u64 t; cvta.to.shared.u64 t, %1; cvt.u32.u64 %0, t; }" : "=r"(a) : "l"(p));
    return a;
}
__device__ __forceinline__ void cpa16(uint32_t s, const void* g) {
    asm volatile("cp.async.cg.shared.global [%0], [%1], 16;" :: "r"(s), "l"(g));
}
#define CPA_COMMIT() asm volatile("cp.async.commit_group;" ::: "memory")

__device__ __forceinline__ void ldsm_x4(uint32_t& r0, uint32_t& r1, uint32_t& r2,
                                        uint32_t& r3, uint32_t addr) {
    asm volatile("ldmatrix.sync.aligned.m8n8.x4.shared.b16 {%0,%1,%2,%3}, [%4];"
                 : "=r"(r0), "=r"(r1), "=r"(r2), "=r"(r3) : "r"(addr));
}
__device__ __forceinline__ void ldsm_x4_t(uint32_t& r0, uint32_t& r1, uint32_t& r2,
                                          uint32_t& r3, uint32_t addr) {
    asm volatile("ldmatrix.sync.aligned.m8n8.x4.trans.shared.b16 {%0,%1,%2,%3}, [%4];"
                 : "=r"(r0), "=r"(r1), "=r"(r2), "=r"(r3) : "r"(addr));
}
__device__ __forceinline__ void mma16816(float* c, const uint32_t* a, const uint32_t* b) {
    asm volatile(
        "mma.sync.aligned.m16n8k16.row.col.f32.f16.f16.f32 "
        "{%0,%1,%2,%3}, {%4,%5,%6,%7}, {%8,%9}, {%0,%1,%2,%3};"
        : "+f"(c[0]), "+f"(c[1]), "+f"(c[2]), "+f"(c[3])
        : "r"(a[0]), "r"(a[1]), "r"(a[2]), "r"(a[3]), "r"(b[0]), "r"(b[1]));
}

// bilinear sample with border masking (matches reference semantics)
__device__ __forceinline__ float bilinear(const float* __restrict__ img,
                                          float py, float px) {
    const float y0f = floorf(py);
    const float x0f = floorf(px);
    const float ly = py - y0f;
    const float lx = px - x0f;
    const int iy0 = (int)y0f, ix0 = (int)x0f;
    const int iy1 = iy0 + 1,  ix1 = ix0 + 1;

    const bool vy0 = (iy0 >= 0) && (iy0 <= H - 1);
    const bool vy1 = (iy1 >= 0) && (iy1 <= H - 1);
    const bool vx0 = (ix0 >= 0) && (ix0 <= W - 1);
    const bool vx1 = (ix1 >= 0) && (ix1 <= W - 1);

    const int yc0 = min(max(iy0, 0), H - 1);
    const int yc1 = min(max(iy1, 0), H - 1);
    const int xc0 = min(max(ix0, 0), W - 1);
    const int xc1 = min(max(ix1, 0), W - 1);

    const float w00 = (1.f - ly) * (1.f - lx) * ((vy0 && vx0) ? 1.f : 0.f);
    const float w01 = (1.f - ly) * lx         * ((vy0 && vx1) ? 1.f : 0.f);
    const float w10 = ly * (1.f - lx)         * ((vy1 && vx0) ? 1.f : 0.f);
    const float w11 = ly * lx                 * ((vy1 && vx1) ? 1.f : 0.f);

    return w00 * img[yc0 * W + xc0] + w01 * img[yc0 * W + xc1] +
           w10 * img[yc1 * W + xc0] + w11 * img[yc1 * W + xc1];
}

// ---------------------------------------------------------------------------
// Kernel 0: fp32 -> fp16 weight convert + zero GN accumulators
// ---------------------------------------------------------------------------
__global__ void wconv_kernel(const float* __restrict__ w) {
    int i = blockIdx.x * 1024 + threadIdx.x;
    if (i < C * CK) g_A[i] = __float2half(w[i]);
    if (blockIdx.x == 0 && threadIdx.x < B * GN) {
        g_gsum[threadIdx.x] = 0.f;
        g_gss[threadIdx.x]  = 0.f;
    }
}

// ---------------------------------------------------------------------------
// Kernel 1: offset field precompute  off[b][g][k][p] = (dy, dx)
// ---------------------------------------------------------------------------
__global__ void off_kernel(const float* __restrict__ shp,
                           const float* __restrict__ w_offset)
{
    const int p  = blockIdx.x * 256 + threadIdx.x;
    const int gk = blockIdx.y;                       // 0..35
    const int b  = blockIdx.z;

    const float* sp = shp + (size_t)b * 4 * HW + p;
    const float s0 = sp[0], s1 = sp[HW], s2 = sp[2 * HW], s3 = sp[3 * HW];

    const float* wo = w_offset + (size_t)gk * 2 * 4;
    const float dy = wo[0] * s0 + wo[1] * s1 + wo[2] * s2 + wo[3] * s3;
    const float dx = wo[4] * s0 + wo[5] * s1 + wo[6] * s2 + wo[7] * s3;

    g_off[((size_t)b * DG * K2 + gk) * HW + p] = make_float2(dy, dx);
}

// ---------------------------------------------------------------------------
// Kernel 2: fused deformable-gather + HMMA GEMM + GN partial stats
//   conv[b][m][p] = sum_ck A[m][ck] * sample(x, off)[ck][p]
// CTA tile: BM=256, BN=64, BK=64; 8 warps (4m x 2n). B tile built in smem.
// ---------------------------------------------------------------------------
constexpr int BM = 256, BN = 64, BK = 64;
constexpr int NT = CK / BK;               // 36 (9 chunks per deform group)
constexpr int A_STRIDE = BK + 8;          // 72 halfs
constexpr int B_STRIDE = BN + 8;          // 72 halfs
constexpr int A_BUF = BM * A_STRIDE;      // 18432 halfs
constexpr int B_BUF = BK * B_STRIDE;      // 4608 halfs
constexpr uint32_t GEMM_SMEM = 2 * (A_BUF + B_BUF) * 2;  // 92160 B

__global__ void __launch_bounds__(256, 2) gemm_kernel(const float* __restrict__ x)
{
    extern __shared__ __half sm[];
    __half* Asm = sm;                     // [2][BM][A_STRIDE]
    __half* Bsm = sm + 2 * A_BUF;         // [2][BK][B_STRIDE]

    const int tid  = threadIdx.x;
    const int lane = tid & 31;
    const int warp = tid >> 5;
    const int n0   = blockIdx.x * BN;
    const int b    = blockIdx.y;
    const int wm   = (warp >> 1) * 64;
    const int wn   = (warp & 1) * 32;

    const uint32_t sA = smem_u32(Asm);
    const uint32_t sB = smem_u32(Bsm);

    // A tile loader (cp.async)
    auto load_A = [&](int kt, int j) {
        const __half* ga = g_A + (size_t)kt * BK;
        const uint32_t dA = sA + j * A_BUF * 2;
        #pragma unroll
        for (int it = 0; it < 8; it++) {
            int c = it * 256 + tid;        // 0..2047
            int r = c >> 3, s = c & 7;
            cpa16(dA + (uint32_t)(r * A_STRIDE + s * 8) * 2,
                  ga + (size_t)r * CK + s * 8);
        }
        CPA_COMMIT();
    };

    // B tile builder: warp handles 8 ck-rows; lane handles 2 positions.
    const int p0 = n0 + lane * 2;
    const int ph = p0 >> 6, pw = p0 & 63;   // p0 and p0+1 share the row h
    auto build_B = [&](int kt, int j) {
        const int g  = kt / 9;              // deform group (chunk-aligned)
        const int cb = (kt % 9) * 64;       // ck offset within group block
        const float* xg = x + ((size_t)b * C + g * CG) * HW;
        const float2* offg = g_off + ((size_t)b * DG + g) * K2 * HW;
        __half* bj = Bsm + j * B_BUF;
        #pragma unroll
        for (int r8 = 0; r8 < 8; r8++) {
            const int r   = warp * 8 + r8;
            const int rem = cb + r;
            const int ci  = rem / 9;
            const int k   = rem - ci * 9;
            const float fki = (float)(k / 3 - 1);
            const float fkj = (float)(k % 3 - 1);
            const float* img = xg + (size_t)ci * HW;
            // two float2 offsets as one float4
            const float4 o = *(const float4*)(offg + (size_t)k * HW + p0);
            const float v0 = bilinear(img, o.x + fki + ph, o.y + fkj + pw);
            const float v1 = bilinear(img, o.z + fki + ph, o.w + fkj + pw + 1.f);
            *(__half2*)(bj + r * B_STRIDE + lane * 2) = __floats2half2_rn(v0, v1);
        }
    };

    float acc[4][4][4];
    #pragma unroll
    for (int i = 0; i < 4; i++)
        #pragma unroll
        for (int n = 0; n < 4; n++)
            #pragma unroll
            for (int q = 0; q < 4; q++) acc[i][n][q] = 0.f;

    build_B(0, 0); load_A(0, 0);
    build_B(1, 1); load_A(1, 1);

    for (int kt = 0; kt < NT; kt++) {
        const int j = kt & 1;
        if (kt + 1 < NT) asm volatile("cp.async.wait_group 1;" ::: "memory");
        else             asm volatile("cp.async.wait_group 0;" ::: "memory");
        __syncthreads();

        const uint32_t aBase = sA + j * A_BUF * 2;
        const uint32_t bBase = sB + j * B_BUF * 2;

        #pragma unroll
        for (int kk = 0; kk < 4; kk++) {
            uint32_t a[4][4];
            #pragma unroll
            for (int i = 0; i < 4; i++) {
                uint32_t addr = aBase +
                    (uint32_t)((wm + i * 16 + (lane & 15)) * A_STRIDE +
                               kk * 16 + (lane >> 4) * 8) * 2;
                ldsm_x4(a[i][0], a[i][1], a[i][2], a[i][3], addr);
            }
            uint32_t bb[4][2];
            #pragma unroll
            for (int p = 0; p < 2; p++) {
                uint32_t addr = bBase +
                    (uint32_t)((kk * 16 + (lane & 15)) * B_STRIDE +
                               wn + p * 16 + (lane >> 4) * 8) * 2;
                uint32_t r0, r1, r2, r3;
                ldsm_x4_t(r0, r1, r2, r3, addr);
                bb[2 * p][0] = r0;     bb[2 * p][1] = r1;
                bb[2 * p + 1][0] = r2; bb[2 * p + 1][1] = r3;
            }
            #pragma unroll
            for (int i = 0; i < 4; i++)
                #pragma unroll
                for (int n = 0; n < 4; n++)
                    mma16816(acc[i][n], a[i], bb[n]);
        }
        __syncthreads();   // all warps done reading buffer j

        if (kt + 2 < NT) {
            build_B(kt + 2, j);
            load_A(kt + 2, j);
        }
    }

    // ---- Epilogue: write conv + fused GN partial stats --------------------
    #pragma unroll
    for (int i = 0; i < 4; i++) {
        const int m = wm + i * 16 + (lane >> 2);
        float* row0 = g_conv + ((size_t)b * C + m) * HW + n0 + wn;
        float* row1 = row0 + (size_t)8 * HW;
        #pragma unroll
        for (int n = 0; n < 4; n++) {
            const int col = n * 8 + (lane & 3) * 2;
            *(float2*)(row0 + col) = make_float2(acc[i][n][0], acc[i][n][1]);
            *(float2*)(row1 + col) = make_float2(acc[i][n][2], acc[i][n][3]);
        }
    }

    float* part = (float*)sm;              // reuse smem: [32 groups][sum,ss]
    if (tid < 64) part[tid] = 0.f;
    __syncthreads();

    #pragma unroll
    for (int i = 0; i < 4; i++) {
        float s0 = 0.f, q0 = 0.f, s1 = 0.f, q1 = 0.f;
        #pragma unroll
        for (int n = 0; n < 4; n++) {
            s0 += acc[i][n][0] + acc[i][n][1];
            q0 += acc[i][n][0] * acc[i][n][0] + acc[i][n][1] * acc[i][n][1];
            s1 += acc[i][n][2] + acc[i][n][3];
            q1 += acc[i][n][2] * acc[i][n][2] + acc[i][n][3] * acc[i][n][3];
        }
        #pragma unroll
        for (int o = 1; o < 4; o <<= 1) {
            s0 += __shfl_xor_sync(0xffffffff, s0, o);
            q0 += __shfl_xor_sync(0xffffffff, q0, o);
            s1 += __shfl_xor_sync(0xffffffff, s1, o);
            q1 += __shfl_xor_sync(0xffffffff, q1, o);
        }
        if ((lane & 3) == 0) {
            const int m0 = wm + i * 16 + (lane >> 2);
            atomicAdd(&part[(m0 >> 3) * 2],           s0);
            atomicAdd(&part[(m0 >> 3) * 2 + 1],       q0);
            atomicAdd(&part[((m0 + 8) >> 3) * 2],     s1);
            atomicAdd(&part[((m0 + 8) >> 3) * 2 + 1], q1);
        }
    }
    __syncthreads();
    if (tid < 32) {
        atomicAdd(&g_gsum[b * GN + tid], part[tid * 2]);
        atomicAdd(&g_gss[b * GN + tid],  part[tid * 2 + 1]);
    }
}

// ---------------------------------------------------------------------------
// Kernel 3: normalize + affine + ReLU (stats finalized inline; one c per block)
// ---------------------------------------------------------------------------
__global__ void gn_norm_kernel(const float* __restrict__ gamma,
                               const float* __restrict__ beta,
                               float* __restrict__ out)
{
    const size_t base = (size_t)blockIdx.x * 1024;   // 1024 floats per block
    const int c  = (int)((base >> 12) & 255);
    const int b  = (int)(base >> 20);
    const int gi = b * GN + (c >> 3);

    const float inv_n = 1.f / (float)(CPG * HW);
    const float mu  = g_gsum[gi] * inv_n;
    const float var = g_gss[gi] * inv_n - mu * mu;
    const float rs  = rsqrtf(var + 1e-5f);
    const float ga  = gamma[c] * rs;
    const float be  = beta[c] - mu * ga;

    const size_t i = base + threadIdx.x * 4;
    float4 v = *(const float4*)(g_conv + i);
    v.x = fmaxf(v.x * ga + be, 0.f);
    v.y = fmaxf(v.y * ga + be, 0.f);
    v.z = fmaxf(v.z * ga + be, 0.f);
    v.w = fmaxf(v.w * ga + be, 0.f);
    *(float4*)(out + i) = v;
}

// ---------------------------------------------------------------------------
extern "C" void kernel_launch(void* const* d_in, const int* in_sizes, int n_in,
                              void* d_out, int out_size)
{
    const float* x        = (const float*)d_in[0];
    const float* shp      = (const float*)d_in[1];
    const float* w_offset = (const float*)d_in[2];
    const float* w_deform = (const float*)d_in[3];
    const float* gamma    = (const float*)d_in[4];
    const float* beta     = (const float*)d_in[5];
    float* out = (float*)d_out;

    static bool attr_set = false;
    if (!attr_set) {
        cudaFuncSetAttribute(gemm_kernel, cudaFuncAttributeMaxDynamicSharedMemorySize,
                             GEMM_SMEM);
        attr_set = true;
    }

    wconv_kernel<<<(C * CK + 1023) / 1024, 1024>>>(w_deform);

    dim3 g1(HW / 256, DG * K2, B);
    off_kernel<<<g1, 256>>>(shp, w_offset);

    dim3 g2(HW / BN, B);                   // (64, 8)
    gemm_kernel<<<g2, 256, GEMM_SMEM>>>(x);

    gn_norm_kernel<<<(unsigned)((size_t)B * C * HW / 1024), 256>>>(gamma, beta, out);
}

// round 6
// speedup vs baseline: 1.2900x; 1.2900x over previous
#include <cuda_runtime.h>
#include <cuda_fp16.h>
#include <cstdint>

// Problem constants
constexpr int B  = 8;
constexpr int C  = 256;
constexpr int H  = 64;
constexpr int W  = 64;
constexpr int HW = H * W;          // 4096
constexpr int K2 = 9;
constexpr int DG = 4;
constexpr int CG = C / DG;         // 64
constexpr int CK = C * K2;         // 2304  (K order: ck' = (g*9+k)*64 + ci)
constexpr int GN = 32;
constexpr int CPG = C / GN;        // 8

// Scratch (static device arrays)
__device__ __align__(16) __half g_col[(size_t)B * CK * HW];   // 151 MB col[b][ck'][p]
__device__ __align__(16) __half g_A[(size_t)C * CK];          // fp16 weights [m][ck']
__device__ __align__(16) float  g_xt[(size_t)B * HW * C];     // 33.5 MB x transposed [b][p][c]
__device__ float g_conv[(size_t)B * C * HW];                  // 33.5 MB conv output
__device__ float g_gsum[B * GN];
__device__ float g_gss[B * GN];

// ---------------------------------------------------------------------------
// PTX helpers (baseline PTX only — toolchain targets compute_103, no tcgen05)
// ---------------------------------------------------------------------------
__device__ __forceinline__ uint32_t smem_u32(const void* p) {
    uint32_t a;
    asm("{ .reg .u64 t; cvta.to.shared.u64 t, %1; cvt.u32.u64 %0, t; }" : "=r"(a) : "l"(p));
    return a;
}
__device__ __forceinline__ void cpa16(uint32_t s, const void* g) {
    asm volatile("cp.async.cg.shared.global [%0], [%1], 16;" :: "r"(s), "l"(g));
}
#define CPA_COMMIT() asm volatile("cp.async.commit_group;" ::: "memory")

__device__ __forceinline__ void ldsm_x4(uint32_t& r0, uint32_t& r1, uint32_t& r2,
                                        uint32_t& r3, uint32_t addr) {
    asm volatile("ldmatrix.sync.aligned.m8n8.x4.shared.b16 {%0,%1,%2,%3}, [%4];"
                 : "=r"(r0), "=r"(r1), "=r"(r2), "=r"(r3) : "r"(addr));
}
__device__ __forceinline__ void ldsm_x4_t(uint32_t& r0, uint32_t& r1, uint32_t& r2,
                                          uint32_t& r3, uint32_t addr) {
    asm volatile("ldmatrix.sync.aligned.m8n8.x4.trans.shared.b16 {%0,%1,%2,%3}, [%4];"
                 : "=r"(r0), "=r"(r1), "=r"(r2), "=r"(r3) : "r"(addr));
}
__device__ __forceinline__ void mma16816(float* c, const uint32_t* a, const uint32_t* b) {
    asm volatile(
        "mma.sync.aligned.m16n8k16.row.col.f32.f16.f16.f32 "
        "{%0,%1,%2,%3}, {%4,%5,%6,%7}, {%8,%9}, {%0,%1,%2,%3};"
        : "+f"(c[0]), "+f"(c[1]), "+f"(c[2]), "+f"(c[3])
        : "r"(a[0]), "r"(a[1]), "r"(a[2]), "r"(a[3]), "r"(b[0]), "r"(b[1]));
}

// 4-channel bilinear gather from transposed image rows (base = x_t[b][.][c0])
__device__ __forceinline__ float4 bilinear4(const float* __restrict__ base,
                                            float py, float px) {
    const float y0f = floorf(py);
    const float x0f = floorf(px);
    const float ly = py - y0f;
    const float lx = px - x0f;
    const int iy0 = (int)y0f, ix0 = (int)x0f;
    const int iy1 = iy0 + 1,  ix1 = ix0 + 1;

    const bool vy0 = (iy0 >= 0) && (iy0 <= H - 1);
    const bool vy1 = (iy1 >= 0) && (iy1 <= H - 1);
    const bool vx0 = (ix0 >= 0) && (ix0 <= W - 1);
    const bool vx1 = (ix1 >= 0) && (ix1 <= W - 1);

    const int yc0 = min(max(iy0, 0), H - 1);
    const int yc1 = min(max(iy1, 0), H - 1);
    const int xc0 = min(max(ix0, 0), W - 1);
    const int xc1 = min(max(ix1, 0), W - 1);

    const float w00 = (1.f - ly) * (1.f - lx) * ((vy0 && vx0) ? 1.f : 0.f);
    const float w01 = (1.f - ly) * lx         * ((vy0 && vx1) ? 1.f : 0.f);
    const float w10 = ly * (1.f - lx)         * ((vy1 && vx0) ? 1.f : 0.f);
    const float w11 = ly * lx                 * ((vy1 && vx1) ? 1.f : 0.f);

    const float4 t00 = *(const float4*)(base + (size_t)(yc0 * W + xc0) * C);
    const float4 t01 = *(const float4*)(base + (size_t)(yc0 * W + xc1) * C);
    const float4 t10 = *(const float4*)(base + (size_t)(yc1 * W + xc0) * C);
    const float4 t11 = *(const float4*)(base + (size_t)(yc1 * W + xc1) * C);

    float4 r;
    r.x = w00 * t00.x + w01 * t01.x + w10 * t10.x + w11 * t11.x;
    r.y = w00 * t00.y + w01 * t01.y + w10 * t10.y + w11 * t11.y;
    r.z = w00 * t00.z + w01 * t01.z + w10 * t10.z + w11 * t11.z;
    r.w = w00 * t00.w + w01 * t01.w + w10 * t10.w + w11 * t11.w;
    return r;
}

// ---------------------------------------------------------------------------
// Kernel 0: weight convert with K reorder  A[m][(g*9+k)*64+ci] = w[m][g*64+ci][k]
//           + zero GN accumulators
// ---------------------------------------------------------------------------
__global__ void wconv_kernel(const float* __restrict__ w) {
    int i = blockIdx.x * 1024 + threadIdx.x;
    if (i < C * CK) {
        const int m   = i / CK;
        const int ckp = i % CK;
        const int gk  = ckp >> 6;
        const int ci  = ckp & 63;
        const int g   = gk / 9;
        const int k   = gk % 9;
        g_A[i] = __float2half(w[((size_t)m * C + g * CG + ci) * K2 + k]);
    }
    if (blockIdx.x == 0 && threadIdx.x < B * GN) {
        g_gsum[threadIdx.x] = 0.f;
        g_gss[threadIdx.x]  = 0.f;
    }
}

// ---------------------------------------------------------------------------
// Kernel 1: transpose x[b][c][p] -> x_t[b][p][c]  (32x32 smem tiles)
// ---------------------------------------------------------------------------
__global__ void transpose_kernel(const float* __restrict__ x) {
    __shared__ float t[32][33];
    const int b  = blockIdx.z;
    const int pB = blockIdx.x * 32;
    const int cB = blockIdx.y * 32;
    const int tx = threadIdx.x, ty = threadIdx.y;   // (32, 8)

    const float* xb = x + (size_t)b * C * HW;
    #pragma unroll
    for (int j = 0; j < 4; j++)
        t[ty + j * 8][tx] = xb[(size_t)(cB + ty + j * 8) * HW + pB + tx];
    __syncthreads();
    float* xtb = g_xt + (size_t)b * HW * C;
    #pragma unroll
    for (int j = 0; j < 4; j++)
        xtb[(size_t)(pB + ty + j * 8) * C + cB + tx] = t[tx][ty + j * 8];
}

// ---------------------------------------------------------------------------
// Kernel 2: im2col — channel-vectorized deformable gather (fp16 half2 output)
// Thread: (gk, 2 adjacent positions, 4 channels). Block 256: 32 positions.
// Grid: (HW/32, 36, B)
// ---------------------------------------------------------------------------
__global__ void __launch_bounds__(256) im2col_kernel(
    const float* __restrict__ shp, const float* __restrict__ w_offset)
{
    const int tid = threadIdx.x;
    const int sub = tid >> 4;            // 0..15 position-pair within block
    const int ci4 = (tid & 15) * 4;      // channel offset (within group)
    const int gk  = blockIdx.y;
    const int b   = blockIdx.z;
    const int g   = gk / 9, k = gk % 9;

    const int p0 = blockIdx.x * 32 + sub * 2;
    const int h  = p0 >> 6, w0 = p0 & 63;

    // shape values (broadcast across the 16 ci lanes)
    const float* sp = shp + (size_t)b * 4 * HW + p0;
    const float s00 = sp[0],        s01 = sp[1];
    const float s10 = sp[HW],       s11 = sp[HW + 1];
    const float s20 = sp[2 * HW],   s21 = sp[2 * HW + 1];
    const float s30 = sp[3 * HW],   s31 = sp[3 * HW + 1];

    const float* wo = w_offset + (size_t)gk * 8;
    const float dy0 = wo[0] * s00 + wo[1] * s10 + wo[2] * s20 + wo[3] * s30;
    const float dy1 = wo[0] * s01 + wo[1] * s11 + wo[2] * s21 + wo[3] * s31;
    const float dx0 = wo[4] * s00 + wo[5] * s10 + wo[6] * s20 + wo[7] * s30;
    const float dx1 = wo[4] * s01 + wo[5] * s11 + wo[6] * s21 + wo[7] * s31;

    const float fki = (float)(k / 3 - 1);
    const float fkj = (float)(k % 3 - 1);

    const float* base = g_xt + (size_t)b * HW * C + g * CG + ci4;
    const float4 v0 = bilinear4(base, dy0 + fki + h, dx0 + fkj + w0);
    const float4 v1 = bilinear4(base, dy1 + fki + h, dx1 + fkj + w0 + 1.f);

    __half* cp = g_col + ((size_t)b * CK + (size_t)gk * 64 + ci4) * HW + p0;
    *(__half2*)(cp)          = __floats2half2_rn(v0.x, v1.x);
    *(__half2*)(cp + HW)     = __floats2half2_rn(v0.y, v1.y);
    *(__half2*)(cp + 2 * HW) = __floats2half2_rn(v0.z, v1.z);
    *(__half2*)(cp + 3 * HW) = __floats2half2_rn(v0.w, v1.w);
}

// ---------------------------------------------------------------------------
// Kernel 3: HMMA GEMM + fused GN partial statistics
// CTA tile: BM=256, BN=64, BK=64; 8 warps (4m x 2n), 64x32 per warp.
// ---------------------------------------------------------------------------
constexpr int BM = 256, BN = 64, BK = 64;
constexpr int NT = CK / BK;               // 36
constexpr int A_STRIDE = BK + 8;          // 72 halfs
constexpr int B_STRIDE = BN + 8;          // 72 halfs
constexpr int A_BUF = BM * A_STRIDE;      // 18432 halfs
constexpr int B_BUF = BK * B_STRIDE;      // 4608 halfs
constexpr uint32_t GEMM_SMEM = 2 * (A_BUF + B_BUF) * 2;  // 92160 B

__global__ void __launch_bounds__(256, 2) gemm_kernel()
{
    extern __shared__ __half sm[];
    __half* Asm = sm;
    __half* Bsm = sm + 2 * A_BUF;

    const int tid  = threadIdx.x;
    const int lane = tid & 31;
    const int warp = tid >> 5;
    const int n0   = blockIdx.x * BN;
    const int b    = blockIdx.y;
    const int wm   = (warp >> 1) * 64;
    const int wn   = (warp & 1) * 32;

    const uint32_t sA = smem_u32(Asm);
    const uint32_t sB = smem_u32(Bsm);

    auto load_tile = [&](int kt, int j) {
        const __half* ga = g_A + (size_t)kt * BK;
        const uint32_t dA = sA + j * A_BUF * 2;
        #pragma unroll
        for (int it = 0; it < 8; it++) {
            int c = it * 256 + tid;
            int r = c >> 3, s = c & 7;
            cpa16(dA + (uint32_t)(r * A_STRIDE + s * 8) * 2,
                  ga + (size_t)r * CK + s * 8);
        }
        const __half* gb = g_col + ((size_t)b * CK + (size_t)kt * BK) * HW + n0;
        const uint32_t dB = sB + j * B_BUF * 2;
        #pragma unroll
        for (int it = 0; it < 2; it++) {
            int c = it * 256 + tid;
            int r = c >> 3, s = c & 7;
            cpa16(dB + (uint32_t)(r * B_STRIDE + s * 8) * 2,
                  gb + (size_t)r * HW + s * 8);
        }
        CPA_COMMIT();
    };

    float acc[4][4][4];
    #pragma unroll
    for (int i = 0; i < 4; i++)
        #pragma unroll
        for (int n = 0; n < 4; n++)
            #pragma unroll
            for (int q = 0; q < 4; q++) acc[i][n][q] = 0.f;

    load_tile(0, 0);

    for (int kt = 0; kt < NT; kt++) {
        const int j = kt & 1;
        if (kt + 1 < NT) {
            load_tile(kt + 1, j ^ 1);
            asm volatile("cp.async.wait_group 1;" ::: "memory");
        } else {
            asm volatile("cp.async.wait_group 0;" ::: "memory");
        }
        __syncthreads();

        const uint32_t aBase = sA + j * A_BUF * 2;
        const uint32_t bBase = sB + j * B_BUF * 2;

        #pragma unroll
        for (int kk = 0; kk < 4; kk++) {
            uint32_t a[4][4];
            #pragma unroll
            for (int i = 0; i < 4; i++) {
                uint32_t addr = aBase +
                    (uint32_t)((wm + i * 16 + (lane & 15)) * A_STRIDE +
                               kk * 16 + (lane >> 4) * 8) * 2;
                ldsm_x4(a[i][0], a[i][1], a[i][2], a[i][3], addr);
            }
            uint32_t bb[4][2];
            #pragma unroll
            for (int p = 0; p < 2; p++) {
                uint32_t addr = bBase +
                    (uint32_t)((kk * 16 + (lane & 15)) * B_STRIDE +
                               wn + p * 16 + (lane >> 4) * 8) * 2;
                uint32_t r0, r1, r2, r3;
                ldsm_x4_t(r0, r1, r2, r3, addr);
                bb[2 * p][0] = r0;     bb[2 * p][1] = r1;
                bb[2 * p + 1][0] = r2; bb[2 * p + 1][1] = r3;
            }
            #pragma unroll
            for (int i = 0; i < 4; i++)
                #pragma unroll
                for (int n = 0; n < 4; n++)
                    mma16816(acc[i][n], a[i], bb[n]);
        }
        __syncthreads();
    }

    // ---- Epilogue: write conv + fused GN partial stats --------------------
    #pragma unroll
    for (int i = 0; i < 4; i++) {
        const int m = wm + i * 16 + (lane >> 2);
        float* row0 = g_conv + ((size_t)b * C + m) * HW + n0 + wn;
        float* row1 = row0 + (size_t)8 * HW;
        #pragma unroll
        for (int n = 0; n < 4; n++) {
            const int col = n * 8 + (lane & 3) * 2;
            *(float2*)(row0 + col) = make_float2(acc[i][n][0], acc[i][n][1]);
            *(float2*)(row1 + col) = make_float2(acc[i][n][2], acc[i][n][3]);
        }
    }

    float* part = (float*)sm;              // reuse smem: [32 groups][sum,ss]
    if (tid < 64) part[tid] = 0.f;
    __syncthreads();

    #pragma unroll
    for (int i = 0; i < 4; i++) {
        float s0 = 0.f, q0 = 0.f, s1 = 0.f, q1 = 0.f;
        #pragma unroll
        for (int n = 0; n < 4; n++) {
            s0 += acc[i][n][0] + acc[i][n][1];
            q0 += acc[i][n][0] * acc[i][n][0] + acc[i][n][1] * acc[i][n][1];
            s1 += acc[i][n][2] + acc[i][n][3];
            q1 += acc[i][n][2] * acc[i][n][2] + acc[i][n][3] * acc[i][n][3];
        }
        #pragma unroll
        for (int o = 1; o < 4; o <<= 1) {
            s0 += __shfl_xor_sync(0xffffffff, s0, o);
            q0 += __shfl_xor_sync(0xffffffff, q0, o);
            s1 += __shfl_xor_sync(0xffffffff, s1, o);
            q1 += __shfl_xor_sync(0xffffffff, q1, o);
        }
        if ((lane & 3) == 0) {
            const int m0 = wm + i * 16 + (lane >> 2);
            atomicAdd(&part[(m0 >> 3) * 2],           s0);
            atomicAdd(&part[(m0 >> 3) * 2 + 1],       q0);
            atomicAdd(&part[((m0 + 8) >> 3) * 2],     s1);
            atomicAdd(&part[((m0 + 8) >> 3) * 2 + 1], q1);
        }
    }
    __syncthreads();
    if (tid < 32) {
        atomicAdd(&g_gsum[b * GN + tid], part[tid * 2]);
        atomicAdd(&g_gss[b * GN + tid],  part[tid * 2 + 1]);
    }
}

// ---------------------------------------------------------------------------
// Kernel 4: normalize + affine + ReLU (stats finalized inline)
// ---------------------------------------------------------------------------
__global__ void gn_norm_kernel(const float* __restrict__ gamma,
                               const float* __restrict__ beta,
                               float* __restrict__ out)
{
    const size_t base = (size_t)blockIdx.x * 1024;   // one channel-quarter per block
    const int c  = (int)((base >> 12) & 255);
    const int b  = (int)(base >> 20);
    const int gi = b * GN + (c >> 3);

    const float inv_n = 1.f / (float)(CPG * HW);
    const float mu  = g_gsum[gi] * inv_n;
    const float var = g_gss[gi] * inv_n - mu * mu;
    const float rs  = rsqrtf(var + 1e-5f);
    const float ga  = gamma[c] * rs;
    const float be  = beta[c] - mu * ga;

    const size_t i = base + threadIdx.x * 4;
    float4 v = *(const float4*)(g_conv + i);
    v.x = fmaxf(v.x * ga + be, 0.f);
    v.y = fmaxf(v.y * ga + be, 0.f);
    v.z = fmaxf(v.z * ga + be, 0.f);
    v.w = fmaxf(v.w * ga + be, 0.f);
    *(float4*)(out + i) = v;
}

// ---------------------------------------------------------------------------
extern "C" void kernel_launch(void* const* d_in, const int* in_sizes, int n_in,
                              void* d_out, int out_size)
{
    const float* x        = (const float*)d_in[0];
    const float* shp      = (const float*)d_in[1];
    const float* w_offset = (const float*)d_in[2];
    const float* w_deform = (const float*)d_in[3];
    const float* gamma    = (const float*)d_in[4];
    const float* beta     = (const float*)d_in[5];
    float* out = (float*)d_out;

    static bool attr_set = false;
    if (!attr_set) {
        cudaFuncSetAttribute(gemm_kernel, cudaFuncAttributeMaxDynamicSharedMemorySize,
                             GEMM_SMEM);
        attr_set = true;
    }

    wconv_kernel<<<(C * CK + 1023) / 1024, 1024>>>(w_deform);

    dim3 gt(HW / 32, C / 32, B);           // (128, 8, 8)
    transpose_kernel<<<gt, dim3(32, 8)>>>(x);

    dim3 g1(HW / 32, DG * K2, B);          // (128, 36, 8)
    im2col_kernel<<<g1, 256>>>(shp, w_offset);

    dim3 g2(HW / BN, B);                   // (64, 8)
    gemm_kernel<<<g2, 256, GEMM_SMEM>>>();

    gn_norm_kernel<<<(unsigned)((size_t)B * C * HW / 1024), 256>>>(gamma, beta, out);
}

// round 7
// speedup vs baseline: 1.7168x; 1.3309x over previous
#include <cuda_runtime.h>
#include <cuda_fp16.h>
#include <cstdint>

// Problem constants
constexpr int B  = 8;
constexpr int C  = 256;
constexpr int H  = 64;
constexpr int W  = 64;
constexpr int HW = H * W;          // 4096
constexpr int K2 = 9;
constexpr int DG = 4;
constexpr int CG = C / DG;         // 64
constexpr int CK = C * K2;         // 2304  (K order: ck' = (g*9+k)*64 + ci)
constexpr int GN = 32;
constexpr int CPG = C / GN;        // 8

// Scratch (static device arrays)
__device__ __align__(16) __half g_col[(size_t)B * CK * HW];   // 151 MB col[b][ck'][p]
__device__ __align__(16) __half g_A[(size_t)C * CK];          // fp16 weights [m][ck']
__device__ __align__(16) float  g_xt[(size_t)B * HW * C];     // 33.5 MB x_t[b][p][c]
__device__ float g_conv[(size_t)B * C * HW];                  // 33.5 MB conv output
__device__ float g_gsum[B * GN];
__device__ float g_gss[B * GN];

// ---------------------------------------------------------------------------
// PTX helpers (baseline PTX only — toolchain targets compute_103, no tcgen05)
// ---------------------------------------------------------------------------
__device__ __forceinline__ uint32_t smem_u32(const void* p) {
    uint32_t a;
    asm("{ .reg .u64 t; cvta.to.shared.u64 t, %1; cvt.u32.u64 %0, t; }" : "=r"(a) : "l"(p));
    return a;
}
__device__ __forceinline__ void cpa16(uint32_t s, const void* g) {
    asm volatile("cp.async.cg.shared.global [%0], [%1], 16;" :: "r"(s), "l"(g));
}
#define CPA_COMMIT() asm volatile("cp.async.commit_group;" ::: "memory")

__device__ __forceinline__ void ldsm_x4(uint32_t& r0, uint32_t& r1, uint32_t& r2,
                                        uint32_t& r3, uint32_t addr) {
    asm volatile("ldmatrix.sync.aligned.m8n8.x4.shared.b16 {%0,%1,%2,%3}, [%4];"
                 : "=r"(r0), "=r"(r1), "=r"(r2), "=r"(r3) : "r"(addr));
}
__device__ __forceinline__ void ldsm_x4_t(uint32_t& r0, uint32_t& r1, uint32_t& r2,
                                          uint32_t& r3, uint32_t addr) {
    asm volatile("ldmatrix.sync.aligned.m8n8.x4.trans.shared.b16 {%0,%1,%2,%3}, [%4];"
                 : "=r"(r0), "=r"(r1), "=r"(r2), "=r"(r3) : "r"(addr));
}
__device__ __forceinline__ void mma16816(float* c, const uint32_t* a, const uint32_t* b) {
    asm volatile(
        "mma.sync.aligned.m16n8k16.row.col.f32.f16.f16.f32 "
        "{%0,%1,%2,%3}, {%4,%5,%6,%7}, {%8,%9}, {%0,%1,%2,%3};"
        : "+f"(c[0]), "+f"(c[1]), "+f"(c[2]), "+f"(c[3])
        : "r"(a[0]), "r"(a[1]), "r"(a[2]), "r"(a[3]), "r"(b[0]), "r"(b[1]));
}

// 4-channel bilinear gather from transposed image (base = x_t[b][.][c0])
__device__ __forceinline__ float4 bilinear4(const float* __restrict__ base,
                                            float py, float px) {
    const float y0f = floorf(py);
    const float x0f = floorf(px);
    const float ly = py - y0f;
    const float lx = px - x0f;
    const int iy0 = (int)y0f, ix0 = (int)x0f;
    const int iy1 = iy0 + 1,  ix1 = ix0 + 1;

    const bool vy0 = (iy0 >= 0) && (iy0 <= H - 1);
    const bool vy1 = (iy1 >= 0) && (iy1 <= H - 1);
    const bool vx0 = (ix0 >= 0) && (ix0 <= W - 1);
    const bool vx1 = (ix1 >= 0) && (ix1 <= W - 1);

    const int yc0 = min(max(iy0, 0), H - 1);
    const int yc1 = min(max(iy1, 0), H - 1);
    const int xc0 = min(max(ix0, 0), W - 1);
    const int xc1 = min(max(ix1, 0), W - 1);

    const float w00 = (1.f - ly) * (1.f - lx) * ((vy0 && vx0) ? 1.f : 0.f);
    const float w01 = (1.f - ly) * lx         * ((vy0 && vx1) ? 1.f : 0.f);
    const float w10 = ly * (1.f - lx)         * ((vy1 && vx0) ? 1.f : 0.f);
    const float w11 = ly * lx                 * ((vy1 && vx1) ? 1.f : 0.f);

    const float4 t00 = *(const float4*)(base + (size_t)(yc0 * W + xc0) * C);
    const float4 t01 = *(const float4*)(base + (size_t)(yc0 * W + xc1) * C);
    const float4 t10 = *(const float4*)(base + (size_t)(yc1 * W + xc0) * C);
    const float4 t11 = *(const float4*)(base + (size_t)(yc1 * W + xc1) * C);

    float4 r;
    r.x = w00 * t00.x + w01 * t01.x + w10 * t10.x + w11 * t11.x;
    r.y = w00 * t00.y + w01 * t01.y + w10 * t10.y + w11 * t11.y;
    r.z = w00 * t00.z + w01 * t01.z + w10 * t10.z + w11 * t11.z;
    r.w = w00 * t00.w + w01 * t01.w + w10 * t10.w + w11 * t11.w;
    return r;
}

// ---------------------------------------------------------------------------
// Kernel 0: weight convert with K reorder + zero GN accumulators
// ---------------------------------------------------------------------------
__global__ void wconv_kernel(const float* __restrict__ w) {
    int i = blockIdx.x * 1024 + threadIdx.x;
    if (i < C * CK) {
        const int m   = i / CK;
        const int ckp = i % CK;
        const int gk  = ckp >> 6;
        const int ci  = ckp & 63;
        const int g   = gk / 9;
        const int k   = gk % 9;
        g_A[i] = __float2half(w[((size_t)m * C + g * CG + ci) * K2 + k]);
    }
    if (blockIdx.x == 0 && threadIdx.x < B * GN) {
        g_gsum[threadIdx.x] = 0.f;
        g_gss[threadIdx.x]  = 0.f;
    }
}

// ---------------------------------------------------------------------------
// Kernel 1: transpose x[b][c][p] -> x_t[b][p][c]
// ---------------------------------------------------------------------------
__global__ void transpose_kernel(const float* __restrict__ x) {
    __shared__ float t[32][33];
    const int b  = blockIdx.z;
    const int pB = blockIdx.x * 32;
    const int cB = blockIdx.y * 32;
    const int tx = threadIdx.x, ty = threadIdx.y;   // (32, 8)

    const float* xb = x + (size_t)b * C * HW;
    #pragma unroll
    for (int j = 0; j < 4; j++)
        t[ty + j * 8][tx] = xb[(size_t)(cB + ty + j * 8) * HW + pB + tx];
    __syncthreads();
    float* xtb = g_xt + (size_t)b * HW * C;
    #pragma unroll
    for (int j = 0; j < 4; j++)
        xtb[(size_t)(pB + ty + j * 8) * C + cB + tx] = t[tx][ty + j * 8];
}

// ---------------------------------------------------------------------------
// Kernel 2: im2col — dense channel-vectorized gather + smem-staged transpose
// Block = (gk, one h-row of 64 positions). Loads: 16 ci-lanes x 16B = 256B/tap.
// Stores: staged in smem, emitted as coalesced 16B uint4 along p.
// Grid: (H=64 rows, 36, B)
// ---------------------------------------------------------------------------
constexpr int SGS = 68;   // smem row stride in halfs (136B: 8B-aligned, low-conflict)

__global__ void __launch_bounds__(256) im2col_kernel(
    const float* __restrict__ shp, const float* __restrict__ w_offset)
{
    __shared__ __half sg[64 * SGS];       // [p_local][ci]

    const int tid = threadIdx.x;
    const int gk  = blockIdx.y;
    const int b   = blockIdx.z;
    const int g   = gk / 9, k = gk % 9;
    const int h   = blockIdx.x;           // block covers p = h*64 .. h*64+63

    const float fki = (float)(k / 3 - 1);
    const float fkj = (float)(k % 3 - 1);

    const int ci4 = (tid & 15) * 4;
    const float* base = g_xt + (size_t)b * HW * C + g * CG + ci4;
    const float* wo = w_offset + (size_t)gk * 8;
    const float wo0 = wo[0], wo1 = wo[1], wo2 = wo[2], wo3 = wo[3];
    const float wo4 = wo[4], wo5 = wo[5], wo6 = wo[6], wo7 = wo[7];

    #pragma unroll
    for (int pi = 0; pi < 2; pi++) {
        const int pair = pi * 16 + (tid >> 4);   // 0..31
        const int pl   = pair * 2;               // even local position
        const int p0   = h * 64 + pl;

        const float* sp = shp + (size_t)b * 4 * HW + p0;
        const float s00 = sp[0],      s01 = sp[1];
        const float s10 = sp[HW],     s11 = sp[HW + 1];
        const float s20 = sp[2 * HW], s21 = sp[2 * HW + 1];
        const float s30 = sp[3 * HW], s31 = sp[3 * HW + 1];

        const float dy0 = wo0 * s00 + wo1 * s10 + wo2 * s20 + wo3 * s30;
        const float dy1 = wo0 * s01 + wo1 * s11 + wo2 * s21 + wo3 * s31;
        const float dx0 = wo4 * s00 + wo5 * s10 + wo6 * s20 + wo7 * s30;
        const float dx1 = wo4 * s01 + wo5 * s11 + wo6 * s21 + wo7 * s31;

        const float4 v0 = bilinear4(base, dy0 + fki + h, dx0 + fkj + pl);
        const float4 v1 = bilinear4(base, dy1 + fki + h, dx1 + fkj + pl + 1.f);

        __half2* d0 = (__half2*)(sg + pl * SGS + ci4);
        d0[0] = __floats2half2_rn(v0.x, v0.y);
        d0[1] = __floats2half2_rn(v0.z, v0.w);
        __half2* d1 = (__half2*)(sg + (pl + 1) * SGS + ci4);
        d1[0] = __floats2half2_rn(v1.x, v1.y);
        d1[1] = __floats2half2_rn(v1.z, v1.w);
    }
    __syncthreads();

    // Readout: transpose to [ci][p], 16B coalesced global stores.
    const int q8 = (tid & 7) * 8;
    #pragma unroll
    for (int it = 0; it < 2; it++) {
        const int r = (tid >> 3) + it * 32;    // output row (ci) 0..63
        __half tmp[8];
        #pragma unroll
        for (int q = 0; q < 8; q++)
            tmp[q] = sg[(q8 + q) * SGS + r];
        *(uint4*)(g_col + ((size_t)b * CK + (size_t)gk * 64 + r) * HW + h * 64 + q8)
            = *(uint4*)tmp;
    }
}

// ---------------------------------------------------------------------------
// Kernel 3: HMMA GEMM + fused GN partial statistics
// BM=128, BN=64, BK=64; 3-stage cp.async pipeline, XOR-swizzled smem,
// one __syncthreads per K-iter, 3 CTAs/SM target.
// ---------------------------------------------------------------------------
constexpr int BM = 128, BN = 64, BK = 64;
constexpr int NT = CK / BK;               // 36
constexpr int NSTG = 3;
constexpr int A_STG = BM * BK;            // 8192 halfs = 16 KB
constexpr int B_STG = BK * BN;            // 4096 halfs = 8 KB
constexpr uint32_t GEMM_SMEM = NSTG * (A_STG + B_STG) * 2;  // 73728 B

__global__ void __launch_bounds__(256, 3) gemm_kernel()
{
    extern __shared__ __half sm[];
    const uint32_t sA = smem_u32(sm);                     // 3 stages of A
    const uint32_t sB = sA + NSTG * A_STG * 2;            // 3 stages of B

    const int tid  = threadIdx.x;
    const int lane = tid & 31;
    const int warp = tid >> 5;
    const int n0   = blockIdx.x * BN;
    const int my   = blockIdx.y;          // m-tile (0/1)
    const int b    = blockIdx.z;
    const int wm   = (warp >> 1) * 32;    // warp m-base within tile
    const int wn   = (warp & 1) * 32;     // warp n-base

    auto load_tile = [&](int kt, int s) {
        const __half* ga = g_A + ((size_t)my * BM) * CK + (size_t)kt * BK;
        const uint32_t dA = sA + s * A_STG * 2;
        #pragma unroll
        for (int it = 0; it < 4; it++) {
            int idx = it * 256 + tid;      // 0..1023
            int r = idx >> 3, u = idx & 7;
            cpa16(dA + (uint32_t)(r * 8 + (u ^ (r & 7))) * 16,
                  ga + (size_t)r * CK + u * 8);
        }
        const __half* gb = g_col + ((size_t)b * CK + (size_t)kt * BK) * HW + n0;
        const uint32_t dB = sB + s * B_STG * 2;
        #pragma unroll
        for (int it = 0; it < 2; it++) {
            int idx = it * 256 + tid;      // 0..511
            int r = idx >> 3, u = idx & 7;
            cpa16(dB + (uint32_t)(r * 8 + (u ^ (r & 7))) * 16,
                  gb + (size_t)r * HW + u * 8);
        }
        CPA_COMMIT();
    };

    float acc[2][4][4];
    #pragma unroll
    for (int i = 0; i < 2; i++)
        #pragma unroll
        for (int n = 0; n < 4; n++)
            #pragma unroll
            for (int q = 0; q < 4; q++) acc[i][n][q] = 0.f;

    load_tile(0, 0);
    load_tile(1, 1);

    for (int kt = 0; kt < NT; kt++) {
        const int s = kt % NSTG;
        if (kt < NT - 1) asm volatile("cp.async.wait_group 1;" ::: "memory");
        else             asm volatile("cp.async.wait_group 0;" ::: "memory");
        __syncthreads();

        const uint32_t aBase = sA + s * A_STG * 2;
        const uint32_t bBase = sB + s * B_STG * 2;

        #pragma unroll
        for (int kk = 0; kk < 4; kk++) {
            uint32_t a[2][4];
            #pragma unroll
            for (int i = 0; i < 2; i++) {
                const int r = wm + i * 16 + (lane & 15);
                const int u = (kk * 2 + (lane >> 4)) ^ (r & 7);
                ldsm_x4(a[i][0], a[i][1], a[i][2], a[i][3],
                        aBase + (uint32_t)(r * 8 + u) * 16);
            }
            uint32_t bb[4][2];
            #pragma unroll
            for (int p = 0; p < 2; p++) {
                const int r = kk * 16 + (lane & 15);
                const int u = ((wn >> 3) + p * 2 + (lane >> 4)) ^ (r & 7);
                uint32_t r0, r1, r2, r3;
                ldsm_x4_t(r0, r1, r2, r3, bBase + (uint32_t)(r * 8 + u) * 16);
                bb[2 * p][0] = r0;     bb[2 * p][1] = r1;
                bb[2 * p + 1][0] = r2; bb[2 * p + 1][1] = r3;
            }
            #pragma unroll
            for (int i = 0; i < 2; i++)
                #pragma unroll
                for (int n = 0; n < 4; n++)
                    mma16816(acc[i][n], a[i], bb[n]);
        }

        if (kt + 2 < NT) load_tile(kt + 2, (kt + 2) % NSTG);
    }

    // ---- Epilogue: write conv + fused GN partial stats --------------------
    #pragma unroll
    for (int i = 0; i < 2; i++) {
        const int ml = wm + i * 16 + (lane >> 2);
        float* row0 = g_conv + ((size_t)b * C + my * BM + ml) * HW + n0 + wn;
        float* row1 = row0 + (size_t)8 * HW;
        #pragma unroll
        for (int n = 0; n < 4; n++) {
            const int col = n * 8 + (lane & 3) * 2;
            *(float2*)(row0 + col) = make_float2(acc[i][n][0], acc[i][n][1]);
            *(float2*)(row1 + col) = make_float2(acc[i][n][2], acc[i][n][3]);
        }
    }

    __syncthreads();                       // safe to reuse stage smem
    float* part = (float*)sm;              // [16 local groups][sum,ss]
    if (tid < 32) part[tid] = 0.f;
    __syncthreads();

    #pragma unroll
    for (int i = 0; i < 2; i++) {
        float s0 = 0.f, q0 = 0.f, s1 = 0.f, q1 = 0.f;
        #pragma unroll
        for (int n = 0; n < 4; n++) {
            s0 += acc[i][n][0] + acc[i][n][1];
            q0 += acc[i][n][0] * acc[i][n][0] + acc[i][n][1] * acc[i][n][1];
            s1 += acc[i][n][2] + acc[i][n][3];
            q1 += acc[i][n][2] * acc[i][n][2] + acc[i][n][3] * acc[i][n][3];
        }
        #pragma unroll
        for (int o = 1; o < 4; o <<= 1) {
            s0 += __shfl_xor_sync(0xffffffff, s0, o);
            q0 += __shfl_xor_sync(0xffffffff, q0, o);
            s1 += __shfl_xor_sync(0xffffffff, s1, o);
            q1 += __shfl_xor_sync(0xffffffff, q1, o);
        }
        if ((lane & 3) == 0) {
            const int ml = wm + i * 16 + (lane >> 2);
            atomicAdd(&part[(ml >> 3) * 2],           s0);
            atomicAdd(&part[(ml >> 3) * 2 + 1],       q0);
            atomicAdd(&part[((ml + 8) >> 3) * 2],     s1);
            atomicAdd(&part[((ml + 8) >> 3) * 2 + 1], q1);
        }
    }
    __syncthreads();
    if (tid < 16) {
        atomicAdd(&g_gsum[b * GN + my * 16 + tid], part[tid * 2]);
        atomicAdd(&g_gss[b * GN + my * 16 + tid],  part[tid * 2 + 1]);
    }
}

// ---------------------------------------------------------------------------
// Kernel 4: normalize + affine + ReLU (stats finalized inline)
// ---------------------------------------------------------------------------
__global__ void gn_norm_kernel(const float* __restrict__ gamma,
                               const float* __restrict__ beta,
                               float* __restrict__ out)
{
    const size_t base = (size_t)blockIdx.x * 1024;
    const int c  = (int)((base >> 12) & 255);
    const int b  = (int)(base >> 20);
    const int gi = b * GN + (c >> 3);

    const float inv_n = 1.f / (float)(CPG * HW);
    const float mu  = g_gsum[gi] * inv_n;
    const float var = g_gss[gi] * inv_n - mu * mu;
    const float rs  = rsqrtf(var + 1e-5f);
    const float ga  = gamma[c] * rs;
    const float be  = beta[c] - mu * ga;

    const size_t i = base + threadIdx.x * 4;
    float4 v = *(const float4*)(g_conv + i);
    v.x = fmaxf(v.x * ga + be, 0.f);
    v.y = fmaxf(v.y * ga + be, 0.f);
    v.z = fmaxf(v.z * ga + be, 0.f);
    v.w = fmaxf(v.w * ga + be, 0.f);
    *(float4*)(out + i) = v;
}

// ---------------------------------------------------------------------------
extern "C" void kernel_launch(void* const* d_in, const int* in_sizes, int n_in,
                              void* d_out, int out_size)
{
    const float* x        = (const float*)d_in[0];
    const float* shp      = (const float*)d_in[1];
    const float* w_offset = (const float*)d_in[2];
    const float* w_deform = (const float*)d_in[3];
    const float* gamma    = (const float*)d_in[4];
    const float* beta     = (const float*)d_in[5];
    float* out = (float*)d_out;

    static bool attr_set = false;
    if (!attr_set) {
        cudaFuncSetAttribute(gemm_kernel, cudaFuncAttributeMaxDynamicSharedMemorySize,
                             GEMM_SMEM);
        attr_set = true;
    }

    wconv_kernel<<<(C * CK + 1023) / 1024, 1024>>>(w_deform);

    dim3 gt(HW / 32, C / 32, B);           // (128, 8, 8)
    transpose_kernel<<<gt, dim3(32, 8)>>>(x);

    dim3 g1(H, DG * K2, B);                // (64, 36, 8)
    im2col_kernel<<<g1, 256>>>(shp, w_offset);

    dim3 g2(HW / BN, C / BM, B);           // (64, 2, 8)
    gemm_kernel<<<g2, 256, GEMM_SMEM>>>();

    gn_norm_kernel<<<(unsigned)((size_t)B * C * HW / 1024), 256>>>(gamma, beta, out);
}

// round 9
// speedup vs baseline: 1.8367x; 1.0698x over previous
#include <cuda_runtime.h>
#include <cuda_fp16.h>
#include <cstdint>

// Problem constants
constexpr int B  = 8;
constexpr int C  = 256;
constexpr int H  = 64;
constexpr int W  = 64;
constexpr int HW = H * W;          // 4096
constexpr int K2 = 9;
constexpr int DG = 4;
constexpr int CG = C / DG;         // 64
constexpr int CK = C * K2;         // 2304  (K order: ck' = (g*9+k)*64 + ci)
constexpr int GN = 32;
constexpr int CPG = C / GN;        // 8

// Scratch (static device arrays)
__device__ __align__(16) __half g_col[(size_t)B * HW * CK];   // 151 MB col[b][p][ck']
__device__ __align__(16) __half g_A[(size_t)C * CK];          // fp16 weights [m][ck']
__device__ __align__(16) float  g_xt[(size_t)B * HW * C];     // 33.5 MB x_t[b][p][c]
__device__ float g_conv[(size_t)B * C * HW];                  // 33.5 MB conv output
__device__ float g_gsum[B * GN];
__device__ float g_gss[B * GN];

// ---------------------------------------------------------------------------
// PTX helpers (baseline PTX only — toolchain targets compute_103, no tcgen05)
// ---------------------------------------------------------------------------
__device__ __forceinline__ uint32_t smem_u32(const void* p) {
    uint32_t a;
    asm("{ .reg .u64 t; cvta.to.shared.u64 t, %1; cvt.u32.u64 %0, t; }" : "=r"(a) : "l"(p));
    return a;
}
__device__ __forceinline__ void cpa16(uint32_t s, const void* g) {
    asm volatile("cp.async.cg.shared.global [%0], [%1], 16;" :: "r"(s), "l"(g));
}
#define CPA_COMMIT() asm volatile("cp.async.commit_group;" ::: "memory")

__device__ __forceinline__ void ldsm_x4(uint32_t& r0, uint32_t& r1, uint32_t& r2,
                                        uint32_t& r3, uint32_t addr) {
    asm volatile("ldmatrix.sync.aligned.m8n8.x4.shared.b16 {%0,%1,%2,%3}, [%4];"
                 : "=r"(r0), "=r"(r1), "=r"(r2), "=r"(r3) : "r"(addr));
}
__device__ __forceinline__ void mma16816(float* c, const uint32_t* a, const uint32_t* b) {
    asm volatile(
        "mma.sync.aligned.m16n8k16.row.col.f32.f16.f16.f32 "
        "{%0,%1,%2,%3}, {%4,%5,%6,%7}, {%8,%9}, {%0,%1,%2,%3};"
        : "+f"(c[0]), "+f"(c[1]), "+f"(c[2]), "+f"(c[3])
        : "r"(a[0]), "r"(a[1]), "r"(a[2]), "r"(a[3]), "r"(b[0]), "r"(b[1]));
}

// 4-channel bilinear gather from transposed image (base = x_t[b][.][c0])
__device__ __forceinline__ float4 bilinear4(const float* __restrict__ base,
                                            float py, float px) {
    const float y0f = floorf(py);
    const float x0f = floorf(px);
    const float ly = py - y0f;
    const float lx = px - x0f;
    const int iy0 = (int)y0f, ix0 = (int)x0f;
    const int iy1 = iy0 + 1,  ix1 = ix0 + 1;

    const bool vy0 = (iy0 >= 0) && (iy0 <= H - 1);
    const bool vy1 = (iy1 >= 0) && (iy1 <= H - 1);
    const bool vx0 = (ix0 >= 0) && (ix0 <= W - 1);
    const bool vx1 = (ix1 >= 0) && (ix1 <= W - 1);

    const int yc0 = min(max(iy0, 0), H - 1);
    const int yc1 = min(max(iy1, 0), H - 1);
    const int xc0 = min(max(ix0, 0), W - 1);
    const int xc1 = min(max(ix1, 0), W - 1);

    const float w00 = (1.f - ly) * (1.f - lx) * ((vy0 && vx0) ? 1.f : 0.f);
    const float w01 = (1.f - ly) * lx         * ((vy0 && vx1) ? 1.f : 0.f);
    const float w10 = ly * (1.f - lx)         * ((vy1 && vx0) ? 1.f : 0.f);
    const float w11 = ly * lx                 * ((vy1 && vx1) ? 1.f : 0.f);

    const float4 t00 = *(const float4*)(base + (size_t)(yc0 * W + xc0) * C);
    const float4 t01 = *(const float4*)(base + (size_t)(yc0 * W + xc1) * C);
    const float4 t10 = *(const float4*)(base + (size_t)(yc1 * W + xc0) * C);
    const float4 t11 = *(const float4*)(base + (size_t)(yc1 * W + xc1) * C);

    float4 r;
    r.x = w00 * t00.x + w01 * t01.x + w10 * t10.x + w11 * t11.x;
    r.y = w00 * t00.y + w01 * t01.y + w10 * t10.y + w11 * t11.y;
    r.z = w00 * t00.z + w01 * t01.z + w10 * t10.z + w11 * t11.z;
    r.w = w00 * t00.w + w01 * t01.w + w10 * t10.w + w11 * t11.w;
    return r;
}

// ---------------------------------------------------------------------------
// Kernel 0: weight convert with K reorder + zero GN accumulators
// ---------------------------------------------------------------------------
__global__ void wconv_kernel(const float* __restrict__ w) {
    int i = blockIdx.x * 1024 + threadIdx.x;
    if (i < C * CK) {
        const int m   = i / CK;
        const int ckp = i % CK;
        const int gk  = ckp >> 6;
        const int ci  = ckp & 63;
        const int g   = gk / 9;
        const int k   = gk % 9;
        g_A[i] = __float2half(w[((size_t)m * C + g * CG + ci) * K2 + k]);
    }
    if (blockIdx.x == 0 && threadIdx.x < B * GN) {
        g_gsum[threadIdx.x] = 0.f;
        g_gss[threadIdx.x]  = 0.f;
    }
}

// ---------------------------------------------------------------------------
// Kernel 1: transpose x[b][c][p] -> x_t[b][p][c]
// ---------------------------------------------------------------------------
__global__ void transpose_kernel(const float* __restrict__ x) {
    __shared__ float t[32][33];
    const int b  = blockIdx.z;
    const int pB = blockIdx.x * 32;
    const int cB = blockIdx.y * 32;
    const int tx = threadIdx.x, ty = threadIdx.y;   // (32, 8)

    const float* xb = x + (size_t)b * C * HW;
    #pragma unroll
    for (int j = 0; j < 4; j++)
        t[ty + j * 8][tx] = xb[(size_t)(cB + ty + j * 8) * HW + pB + tx];
    __syncthreads();
    float* xtb = g_xt + (size_t)b * HW * C;
    #pragma unroll
    for (int j = 0; j < 4; j++)
        xtb[(size_t)(pB + ty + j * 8) * C + cB + tx] = t[tx][ty + j * 8];
}

// ---------------------------------------------------------------------------
// Kernel 2: im2col — dense gather, direct p-major stores (no smem staging)
// col[b][p][gk*64+ci]. Thread: (gk, 2 positions, 4 channels).
// Loads: 16 ci-lanes x 16B = 256B per tap. Stores: 8B, dense across ci lanes.
// Grid: (H=64, 36, B)
// ---------------------------------------------------------------------------
__global__ void __launch_bounds__(256) im2col_kernel(
    const float* __restrict__ shp, const float* __restrict__ w_offset)
{
    const int tid = threadIdx.x;
    const int gk  = blockIdx.y;
    const int b   = blockIdx.z;
    const int g   = gk / 9, k = gk % 9;
    const int h   = blockIdx.x;

    const float fki = (float)(k / 3 - 1);
    const float fkj = (float)(k % 3 - 1);

    const int ci4 = (tid & 15) * 4;
    const float* base = g_xt + (size_t)b * HW * C + g * CG + ci4;
    const float* wo = w_offset + (size_t)gk * 8;
    const float wo0 = wo[0], wo1 = wo[1], wo2 = wo[2], wo3 = wo[3];
    const float wo4 = wo[4], wo5 = wo[5], wo6 = wo[6], wo7 = wo[7];

    #pragma unroll
    for (int pi = 0; pi < 2; pi++) {
        const int pair = pi * 16 + (tid >> 4);   // 0..31
        const int pl   = pair * 2;
        const int p0   = h * 64 + pl;

        const float* sp = shp + (size_t)b * 4 * HW + p0;
        const float s00 = sp[0],      s01 = sp[1];
        const float s10 = sp[HW],     s11 = sp[HW + 1];
        const float s20 = sp[2 * HW], s21 = sp[2 * HW + 1];
        const float s30 = sp[3 * HW], s31 = sp[3 * HW + 1];

        const float dy0 = wo0 * s00 + wo1 * s10 + wo2 * s20 + wo3 * s30;
        const float dy1 = wo0 * s01 + wo1 * s11 + wo2 * s21 + wo3 * s31;
        const float dx0 = wo4 * s00 + wo5 * s10 + wo6 * s20 + wo7 * s30;
        const float dx1 = wo4 * s01 + wo5 * s11 + wo6 * s21 + wo7 * s31;

        const float4 v0 = bilinear4(base, dy0 + fki + h, dx0 + fkj + pl);
        const float4 v1 = bilinear4(base, dy1 + fki + h, dx1 + fkj + pl + 1.f);

        __half* c0 = g_col + ((size_t)b * HW + p0) * CK + gk * 64 + ci4;
        {
            __half2 t2[2] = { __floats2half2_rn(v0.x, v0.y),
                              __floats2half2_rn(v0.z, v0.w) };
            *(uint2*)c0 = *(uint2*)t2;
        }
        __half* c1 = c0 + CK;
        {
            __half2 t2[2] = { __floats2half2_rn(v1.x, v1.y),
                              __floats2half2_rn(v1.z, v1.w) };
            *(uint2*)c1 = *(uint2*)t2;
        }
    }
}

// ---------------------------------------------------------------------------
// Kernel 3: HMMA GEMM + fused GN partial statistics
// BM=128, BN=64, BK=64; 3-stage cp.async pipeline, XOR-swizzled smem.
// A: [m][k] K-major (non-trans ldsm). B: col[b][p][ck] => [n][k] n-major
// in smem, consumed with NON-trans ldsm (fragment remap r0,r2 / r1,r3).
// ---------------------------------------------------------------------------
constexpr int BM = 128, BN = 64, BK = 64;
constexpr int NT = CK / BK;               // 36
constexpr int NSTG = 3;
constexpr int A_STG = BM * BK;            // 16 KB
constexpr int B_STG = BN * BK;            // 8 KB  ([n=64 rows][k=64])
constexpr uint32_t GEMM_SMEM = NSTG * (A_STG + B_STG) * 2;  // 73728 B

__global__ void __launch_bounds__(256, 3) gemm_kernel()
{
    extern __shared__ __half sm[];
    const uint32_t sA = smem_u32(sm);
    const uint32_t sB = sA + NSTG * A_STG * 2;

    const int tid  = threadIdx.x;
    const int lane = tid & 31;
    const int warp = tid >> 5;
    const int n0   = blockIdx.x * BN;
    const int my   = blockIdx.y;          // m-tile (0/1)
    const int b    = blockIdx.z;
    const int wm   = (warp >> 1) * 32;
    const int wn   = (warp & 1) * 32;

    auto load_tile = [&](int kt, int s) {
        const __half* ga = g_A + ((size_t)my * BM) * CK + (size_t)kt * BK;
        const uint32_t dA = sA + s * A_STG * 2;
        #pragma unroll
        for (int it = 0; it < 4; it++) {
            int idx = it * 256 + tid;      // 0..1023
            int r = idx >> 3, u = idx & 7;
            cpa16(dA + (uint32_t)(r * 8 + (u ^ (r & 7))) * 16,
                  ga + (size_t)r * CK + u * 8);
        }
        // B rows are positions p (n-major): row r = p-local, 64 contiguous ck
        const __half* gb = g_col + ((size_t)b * HW + n0) * CK + (size_t)kt * BK;
        const uint32_t dB = sB + s * B_STG * 2;
        #pragma unroll
        for (int it = 0; it < 2; it++) {
            int idx = it * 256 + tid;      // 0..511
            int r = idx >> 3, u = idx & 7;
            cpa16(dB + (uint32_t)(r * 8 + (u ^ (r & 7))) * 16,
                  gb + (size_t)r * CK + u * 8);
        }
        CPA_COMMIT();
    };

    float acc[2][4][4];
    #pragma unroll
    for (int i = 0; i < 2; i++)
        #pragma unroll
        for (int n = 0; n < 4; n++)
            #pragma unroll
            for (int q = 0; q < 4; q++) acc[i][n][q] = 0.f;

    load_tile(0, 0);
    load_tile(1, 1);

    for (int kt = 0; kt < NT; kt++) {
        const int s = kt % NSTG;
        if (kt < NT - 1) asm volatile("cp.async.wait_group 1;" ::: "memory");
        else             asm volatile("cp.async.wait_group 0;" ::: "memory");
        __syncthreads();

        const uint32_t aBase = sA + s * A_STG * 2;
        const uint32_t bBase = sB + s * B_STG * 2;

        #pragma unroll
        for (int kk = 0; kk < 4; kk++) {
            uint32_t a[2][4];
            #pragma unroll
            for (int i = 0; i < 2; i++) {
                const int r = wm + i * 16 + (lane & 15);
                const int u = (kk * 2 + (lane >> 4)) ^ (r & 7);
                ldsm_x4(a[i][0], a[i][1], a[i][2], a[i][3],
                        aBase + (uint32_t)(r * 8 + u) * 16);
            }
            uint32_t bb[4][2];
            #pragma unroll
            for (int p = 0; p < 2; p++) {
                const int r = wn + p * 16 + (lane & 15);   // n row
                const int u = (kk * 2 + (lane >> 4)) ^ (r & 7);
                uint32_t r0, r1, r2, r3;
                ldsm_x4(r0, r1, r2, r3, bBase + (uint32_t)(r * 8 + u) * 16);
                bb[2 * p][0] = r0;     bb[2 * p][1] = r2;
                bb[2 * p + 1][0] = r1; bb[2 * p + 1][1] = r3;
            }
            #pragma unroll
            for (int i = 0; i < 2; i++)
                #pragma unroll
                for (int n = 0; n < 4; n++)
                    mma16816(acc[i][n], a[i], bb[n]);
        }

        if (kt + 2 < NT) load_tile(kt + 2, (kt + 2) % NSTG);
    }

    // ---- Epilogue: write conv + fused GN partial stats --------------------
    #pragma unroll
    for (int i = 0; i < 2; i++) {
        const int ml = wm + i * 16 + (lane >> 2);
        float* row0 = g_conv + ((size_t)b * C + my * BM + ml) * HW + n0 + wn;
        float* row1 = row0 + (size_t)8 * HW;
        #pragma unroll
        for (int n = 0; n < 4; n++) {
            const int col = n * 8 + (lane & 3) * 2;
            *(float2*)(row0 + col) = make_float2(acc[i][n][0], acc[i][n][1]);
            *(float2*)(row1 + col) = make_float2(acc[i][n][2], acc[i][n][3]);
        }
    }

    __syncthreads();
    float* part = (float*)sm;              // [16 local groups][sum,ss]
    if (tid < 32) part[tid] = 0.f;
    __syncthreads();

    #pragma unroll
    for (int i = 0; i < 2; i++) {
        float s0 = 0.f, q0 = 0.f, s1 = 0.f, q1 = 0.f;
        #pragma unroll
        for (int n = 0; n < 4; n++) {
            s0 += acc[i][n][0] + acc[i][n][1];
            q0 += acc[i][n][0] * acc[i][n][0] + acc[i][n][1] * acc[i][n][1];
            s1 += acc[i][n][2] + acc[i][n][3];
            q1 += acc[i][n][2] * acc[i][n][2] + acc[i][n][3] * acc[i][n][3];
        }
        #pragma unroll
        for (int o = 1; o < 4; o <<= 1) {
            s0 += __shfl_xor_sync(0xffffffff, s0, o);
            q0 += __shfl_xor_sync(0xffffffff, q0, o);
            s1 += __shfl_xor_sync(0xffffffff, s1, o);
            q1 += __shfl_xor_sync(0xffffffff, q1, o);
        }
        if ((lane & 3) == 0) {
            const int ml = wm + i * 16 + (lane >> 2);
            atomicAdd(&part[(ml >> 3) * 2],           s0);
            atomicAdd(&part[(ml >> 3) * 2 + 1],       q0);
            atomicAdd(&part[((ml + 8) >> 3) * 2],     s1);
            atomicAdd(&part[((ml + 8) >> 3) * 2 + 1], q1);
        }
    }
    __syncthreads();
    if (tid < 16) {
        atomicAdd(&g_gsum[b * GN + my * 16 + tid], part[tid * 2]);
        atomicAdd(&g_gss[b * GN + my * 16 + tid],  part[tid * 2 + 1]);
    }
}

// ---------------------------------------------------------------------------
// Kernel 4: normalize + affine + ReLU (stats finalized inline)
// ---------------------------------------------------------------------------
__global__ void gn_norm_kernel(const float* __restrict__ gamma,
                               const float* __restrict__ beta,
                               float* __restrict__ out)
{
    const size_t base = (size_t)blockIdx.x * 1024;
    const int c  = (int)((base >> 12) & 255);
    const int b  = (int)(base >> 20);
    const int gi = b * GN + (c >> 3);

    const float inv_n = 1.f / (float)(CPG * HW);
    const float mu  = g_gsum[gi] * inv_n;
    const float var = g_gss[gi] * inv_n - mu * mu;
    const float rs  = rsqrtf(var + 1e-5f);
    const float ga  = gamma[c] * rs;
    const float be  = beta[c] - mu * ga;

    const size_t i = base + threadIdx.x * 4;
    float4 v = *(const float4*)(g_conv + i);
    v.x = fmaxf(v.x * ga + be, 0.f);
    v.y = fmaxf(v.y * ga + be, 0.f);
    v.z = fmaxf(v.z * ga + be, 0.f);
    v.w = fmaxf(v.w * ga + be, 0.f);
    *(float4*)(out + i) = v;
}

// ---------------------------------------------------------------------------
extern "C" void kernel_launch(void* const* d_in, const int* in_sizes, int n_in,
                              void* d_out, int out_size)
{
    const float* x        = (const float*)d_in[0];
    const float* shp      = (const float*)d_in[1];
    const float* w_offset = (const float*)d_in[2];
    const float* w_deform = (const float*)d_in[3];
    const float* gamma    = (const float*)d_in[4];
    const float* beta     = (const float*)d_in[5];
    float* out = (float*)d_out;

    static bool attr_set = false;
    if (!attr_set) {
        cudaFuncSetAttribute(gemm_kernel, cudaFuncAttributeMaxDynamicSharedMemorySize,
                             GEMM_SMEM);
        attr_set = true;
    }

    wconv_kernel<<<(C * CK + 1023) / 1024, 1024>>>(w_deform);

    dim3 gt(HW / 32, C / 32, B);           // (128, 8, 8)
    transpose_kernel<<<gt, dim3(32, 8)>>>(x);

    dim3 g1(H, DG * K2, B);                // (64, 36, 8)
    im2col_kernel<<<g1, 256>>>(shp, w_offset);

    dim3 g2(HW / BN, C / BM, B);           // (64, 2, 8)
    gemm_kernel<<<g2, 256, GEMM_SMEM>>>();

    gn_norm_kernel<<<(unsigned)((size_t)B * C * HW / 1024), 256>>>(gamma, beta, out);
}